// round 16
// baseline (speedup 1.0000x reference)
#include <cuda_runtime.h>
#include <cuda_fp16.h>
#include <cstdint>
#include <cstddef>

// Problem constants
#define B_   16
#define S_   2048
#define DM   64
#define HEAD 1024
#define QKVW 3072   // 3 * HEAD

// ---------------------------------------------------------------------------
// Scratch (device globals; no runtime allocation allowed)
// ---------------------------------------------------------------------------
__device__ __align__(16) __half g_qh[(size_t)B_ * S_ * HEAD];
__device__ __align__(16) __half g_ql[(size_t)B_ * S_ * HEAD];
__device__ __align__(16) __half g_kh[(size_t)B_ * S_ * HEAD];
__device__ __align__(16) __half g_kl[(size_t)B_ * S_ * HEAD];
__device__ __align__(16) __half g_vth[(size_t)B_ * HEAD * S_];  // V^T [b][n][k] fp16
__device__ __align__(16) float  g_L [(size_t)B_ * S_ * S_];     // fp32 logits
__device__ __align__(16) __half g_Ph[(size_t)B_ * S_ * S_];     // probs (fp16)

// ---------------------------------------------------------------------------
// PTX helpers (sm_80-compatible: cp.async, ldmatrix, mma.sync)
// ---------------------------------------------------------------------------
__device__ __forceinline__ uint32_t smem_u32(const void* p) {
    return (uint32_t)__cvta_generic_to_shared(p);
}

__device__ __forceinline__ void cp_async16(uint32_t dst, const void* src) {
    asm volatile("cp.async.cg.shared.global [%0], [%1], 16;"
                 :: "r"(dst), "l"(src) : "memory");
}
__device__ __forceinline__ void cp_commit() {
    asm volatile("cp.async.commit_group;" ::: "memory");
}
__device__ __forceinline__ void cp_wait2() {
    asm volatile("cp.async.wait_group 2;" ::: "memory");
}
__device__ __forceinline__ void cp_wait1() {
    asm volatile("cp.async.wait_group 1;" ::: "memory");
}
__device__ __forceinline__ void cp_wait0() {
    asm volatile("cp.async.wait_group 0;" ::: "memory");
}

__device__ __forceinline__ void ldm_x4(uint32_t* f, uint32_t addr) {
    asm volatile("ldmatrix.sync.aligned.m8n8.x4.shared.b16 {%0,%1,%2,%3}, [%4];"
                 : "=r"(f[0]), "=r"(f[1]), "=r"(f[2]), "=r"(f[3]) : "r"(addr));
}

// fp32-accumulator HMMA (main product)
__device__ __forceinline__ void mma16816(float* c, const uint32_t* a,
                                         uint32_t b0, uint32_t b1) {
    asm volatile(
        "mma.sync.aligned.m16n8k16.row.col.f32.f16.f16.f32 "
        "{%0,%1,%2,%3}, {%4,%5,%6,%7}, {%8,%9}, {%0,%1,%2,%3};"
        : "+f"(c[0]), "+f"(c[1]), "+f"(c[2]), "+f"(c[3])
        : "r"(a[0]), "r"(a[1]), "r"(a[2]), "r"(a[3]), "r"(b0), "r"(b1));
}

// fp16-accumulator HMMA (correction products; small magnitudes)
__device__ __forceinline__ void mma16816_h(uint32_t* c, const uint32_t* a,
                                           uint32_t b0, uint32_t b1) {
    asm volatile(
        "mma.sync.aligned.m16n8k16.row.col.f16.f16.f16.f16 "
        "{%0,%1}, {%2,%3,%4,%5}, {%6,%7}, {%0,%1};"
        : "+r"(c[0]), "+r"(c[1])
        : "r"(a[0]), "r"(a[1]), "r"(a[2]), "r"(a[3]), "r"(b0), "r"(b1));
}

// ldmatrix lane address inside an SW128-swizzled tile (rows of 128 bytes).
// rowbase: first row of the 16-row block; ks: 16-element k-step (0..3).
__device__ __forceinline__ uint32_t ldm_addr(uint32_t matbase, int rowbase,
                                             int ks, int lane) {
    int j = lane >> 3, r = lane & 7;
    int row = rowbase + (j & 1) * 8 + r;
    uint32_t off = (uint32_t)(row * 128 + ks * 32 + (j >> 1) * 16);
    off ^= (off >> 3) & 0x70;
    return matbase + off;
}

// ---------------------------------------------------------------------------
// split-store helper: fp32 -> (hi, lo) fp16 pairs, 4 at a time (8B stores)
// ---------------------------------------------------------------------------
__device__ __forceinline__ void store_split4(__half* h, __half* l, const float* v) {
    union { __half b[4]; uint2 u; } H, L;
#pragma unroll
    for (int r = 0; r < 4; r++) {
        H.b[r] = __float2half_rn(v[r]);
        L.b[r] = __float2half_rn(v[r] - __half2float(H.b[r]));
    }
    *(uint2*)h = H.u;
    *(uint2*)l = L.u;
}

// ---------------------------------------------------------------------------
// Kernel 1: qkv = x @ W (fp32 SIMT). Epilogue: q/k -> split-fp16 hi/lo;
// V -> fp16 written DIRECTLY TRANSPOSED into g_vth (vtrans kernel fused away).
// ---------------------------------------------------------------------------
__global__ __launch_bounds__(256, 2) void qkv_proj_kernel(const float* __restrict__ x,
                                                          const float* __restrict__ W) {
    __shared__ float xs[16][132];
    __shared__ float ws[16][132];
    const int m0 = blockIdx.y * 128;
    const int n0 = blockIdx.x * 128;
    const int tid = threadIdx.x;
    const int tx = tid & 15, ty = tid >> 4;

    float acc[8][8];
#pragma unroll
    for (int i = 0; i < 8; i++)
#pragma unroll
        for (int j = 0; j < 8; j++) acc[i][j] = 0.f;

    for (int d0 = 0; d0 < DM; d0 += 16) {
#pragma unroll
        for (int t = 0; t < 2; t++) {
            int idx = tid + t * 256;
            int row = idx >> 2, dg = (idx & 3) * 4;
            float4 v = *(const float4*)&x[(size_t)(m0 + row) * DM + d0 + dg];
            xs[dg + 0][row] = v.x; xs[dg + 1][row] = v.y;
            xs[dg + 2][row] = v.z; xs[dg + 3][row] = v.w;
        }
#pragma unroll
        for (int t = 0; t < 2; t++) {
            int idx = tid + t * 256;
            int kk = idx >> 5, ng = (idx & 31) * 4;
            *(float4*)&ws[kk][ng] = *(const float4*)&W[(size_t)(d0 + kk) * QKVW + n0 + ng];
        }
        __syncthreads();
#pragma unroll
        for (int d = 0; d < 16; d++) {
            float a[8], bb[8];
            *(float4*)&a[0]  = *(const float4*)&xs[d][ty * 4];
            *(float4*)&a[4]  = *(const float4*)&xs[d][64 + ty * 4];
            *(float4*)&bb[0] = *(const float4*)&ws[d][tx * 4];
            *(float4*)&bb[4] = *(const float4*)&ws[d][64 + tx * 4];
#pragma unroll
            for (int i = 0; i < 8; i++)
#pragma unroll
                for (int j = 0; j < 8; j++) acc[i][j] += a[i] * bb[j];
        }
        __syncthreads();
    }

    const int region = n0 >> 10;   // 0=q, 1=k, 2=v (128-tiles never straddle)
    const int nn = n0 & 1023;
    if (region == 2) {
        // V^T: write fp16 directly to g_vth[b][n][s]; m is the contiguous axis.
        const int bb = m0 >> 11;           // batch (S=2048, tiles never straddle)
        const int s0 = m0 & 2047;          // seq offset of tile start
#pragma unroll
        for (int j = 0; j < 8; j++) {
            int n = nn + ((j < 4) ? (tx * 4 + j) : (64 + tx * 4 + j - 4));
            union { __half h[4]; uint2 u; } L0, L1;
#pragma unroll
            for (int i = 0; i < 4; i++) {
                L0.h[i] = __float2half_rn(acc[i][j]);
                L1.h[i] = __float2half_rn(acc[i + 4][j]);
            }
            size_t basev = ((size_t)(bb * HEAD + n)) * S_;
            *(uint2*)&g_vth[basev + s0 + ty * 4]      = L0.u;
            *(uint2*)&g_vth[basev + s0 + 64 + ty * 4] = L1.u;
        }
    } else {
        __half* hbb = (region == 0 ? g_qh : g_kh);
        __half* lbb = (region == 0 ? g_ql : g_kl);
#pragma unroll
        for (int i = 0; i < 8; i++) {
            int r = m0 + ((i < 4) ? (ty * 4 + i) : (64 + ty * 4 + i - 4));
            __half* hb = hbb + (size_t)r * HEAD + nn;
            __half* lb = lbb + (size_t)r * HEAD + nn;
            store_split4(hb + tx * 4,      lb + tx * 4,      &acc[i][0]);
            store_split4(hb + 64 + tx * 4, lb + 64 + tx * 4, &acc[i][4]);
        }
    }
}

// ---------------------------------------------------------------------------
// HMMA split-fp16 GEMM, 128x128 CTA tile, 256 threads (8 warps of 64x32),
// K-chunks of 64, 3-stage cp.async pipeline, SW128 smem.
//   IS_QK: 4 matrices (qh,ql,kh,kl): f32 hh + f16-acc (al*bh + ah*bl)
//          -> g_L x0.25  [packed upper-triangular tile grid]
//   else : 2 matrices (Ph,Vh): single f32 hh product -> pv_out
//          (P_lo dropped: half-ulp of fp16 probs, ~1.4e-4 relative)
//          [k starts at 128-aligned diagonal]
// ---------------------------------------------------------------------------
#define MATB   16384                  // 128 rows x 128B

template <bool IS_QK>
__global__ void __launch_bounds__(256, 1) attn_hmma_kernel(float* __restrict__ pv_out) {
    constexpr int NMAT  = IS_QK ? 4 : 2;
    constexpr int STAGE = NMAT * MATB;

    int bm, bn, b;
    if (IS_QK) {
        // packed upper-tri grid: per batch, tiles (bm, bn) with bn >= bm
        int t = blockIdx.x;
        b = blockIdx.y;
        bm = 0;
#pragma unroll 1
        for (; bm < 16; bm++) {
            int cnt = 16 - bm;
            if (t < cnt) break;
            t -= cnt;
        }
        bn = bm + t;
    } else {
        bn = blockIdx.x; bm = blockIdx.y; b = blockIdx.z;
    }

    extern __shared__ __align__(16) char dyn[];
    const uint32_t dynb = smem_u32(dyn);
    const uint32_t tileb = (dynb + 1023) & ~1023u;

    const int tid = threadIdx.x, wid = tid >> 5, lane = tid & 31;
    const int m0 = bm * 128, n0 = bn * 128;
    const int m_off = (wid >> 2) * 64;   // warp rows: 0 or 64
    const int n_off = (wid & 3) * 32;    // warp cols: 0,32,64,96

    const __half* gmat[NMAT];
    size_t strd;
    int kstart, NC;
    if (IS_QK) {
        size_t ab  = ((size_t)(b * S_ + m0)) * HEAD;
        size_t bb2 = ((size_t)(b * S_ + n0)) * HEAD;
        gmat[0] = g_qh + ab; gmat[1] = g_ql + ab;
        gmat[2] = g_kh + bb2; gmat[3] = g_kl + bb2;
        strd = HEAD; kstart = 0; NC = HEAD / 64;
    } else {
        size_t ab  = ((size_t)(b * S_ + m0)) * S_;
        size_t bb2 = ((size_t)(b * HEAD + n0)) * S_;
        gmat[0] = g_Ph + ab; gmat[1] = g_vth + bb2;
        strd = S_; kstart = m0; NC = (S_ - m0) / 64;
    }

    float acc[4][4][4];          // f32 main accumulators
    uint32_t accl[4][4][2];      // f16x2 correction accumulators (QK only)
#pragma unroll
    for (int i = 0; i < 4; i++)
#pragma unroll
        for (int p = 0; p < 4; p++) {
#pragma unroll
            for (int r = 0; r < 4; r++) acc[i][p][r] = 0.f;
            if (IS_QK) { accl[i][p][0] = 0u; accl[i][p][1] = 0u; }
        }

    // chunk loader: NMAT matrices x 128 rows x 64 fp16, SW128, cp.async
    auto load_chunk = [&](int c, int buf) {
        const int k0 = kstart + c * 64;
        uint32_t sb = tileb + buf * STAGE;
#pragma unroll
        for (int mat = 0; mat < NMAT; mat++) {
            const __half* g = gmat[mat] + k0;
            uint32_t mb = sb + mat * MATB;
#pragma unroll
            for (int t = 0; t < 4; t++) {
                int idx = t * 256 + tid;
                int row = idx >> 3, pc = idx & 7;
                uint32_t off = (uint32_t)(row * 128 + pc * 16);
                off ^= (off >> 3) & 0x70;
                cp_async16(mb + off, g + (size_t)row * strd + pc * 8);
            }
        }
        cp_commit();
    };

    load_chunk(0, 0);
    if (NC > 1) load_chunk(1, 1);

    for (int c = 0; c < NC; ++c) {
        const int buf = c % 3;
        if (c + 2 < NC) load_chunk(c + 2, (c + 2) % 3);
        {
            int pend = NC - 1 - c; if (pend > 2) pend = 2;
            if (pend == 2) cp_wait2();
            else if (pend == 1) cp_wait1();
            else cp_wait0();
        }
        __syncthreads();

        const uint32_t base = tileb + buf * STAGE;
        const uint32_t bAh = base;
        const uint32_t bAl = base + MATB;                       // QK only
        const uint32_t bBh = base + (IS_QK ? 2 : 1) * MATB;
        const uint32_t bBl = base + 3 * MATB;                   // QK only

#pragma unroll
        for (int ks = 0; ks < 4; ks++) {
            uint32_t ah[4][4], al[4][4];
#pragma unroll
            for (int i = 0; i < 4; i++) {
                ldm_x4(ah[i], ldm_addr(bAh, m_off + i * 16, ks, lane));
                if (IS_QK) ldm_x4(al[i], ldm_addr(bAl, m_off + i * 16, ks, lane));
            }
#pragma unroll
            for (int p2 = 0; p2 < 2; p2++) {
                uint32_t bh[4], bl[4];
                ldm_x4(bh, ldm_addr(bBh, n_off + p2 * 16, ks, lane));
                if (IS_QK) ldm_x4(bl, ldm_addr(bBl, n_off + p2 * 16, ks, lane));
#pragma unroll
                for (int i = 0; i < 4; i++)
#pragma unroll
                    for (int sb2 = 0; sb2 < 2; sb2++) {
                        const int p = p2 * 2 + sb2;
                        mma16816(acc[i][p], ah[i], bh[sb2], bh[2 + sb2]);
                        if (IS_QK) {
                            mma16816_h(accl[i][p], al[i], bh[sb2], bh[2 + sb2]);
                            mma16816_h(accl[i][p], ah[i], bl[sb2], bl[2 + sb2]);
                        }
                    }
            }
        }
        __syncthreads();
    }

    // epilogue
#pragma unroll
    for (int i = 0; i < 4; i++) {
        int gm = m0 + m_off + i * 16 + (lane >> 2);
#pragma unroll
        for (int p = 0; p < 4; p++) {
            int gn = n0 + n_off + p * 8 + (lane & 3) * 2;
            if (IS_QK) {
                float2 c0 = __half22float2(*(__half2*)&accl[i][p][0]);
                float2 c1 = __half22float2(*(__half2*)&accl[i][p][1]);
                float2 lo = make_float2(0.25f * (acc[i][p][0] + c0.x),
                                        0.25f * (acc[i][p][1] + c0.y));
                float2 hi = make_float2(0.25f * (acc[i][p][2] + c1.x),
                                        0.25f * (acc[i][p][3] + c1.y));
                float* d0 = g_L + ((size_t)(b * S_ + gm)) * S_ + gn;
                *(float2*)d0 = lo;
                *(float2*)(d0 + 8 * S_) = hi;
            } else {
                float2 lo = make_float2(acc[i][p][0], acc[i][p][1]);
                float2 hi = make_float2(acc[i][p][2], acc[i][p][3]);
                float* d0 = pv_out + ((size_t)(b * S_ + gm)) * HEAD + gn;
                *(float2*)d0 = lo;
                *(float2*)(d0 + 8 * HEAD) = hi;
            }
        }
    }
}

// ---------------------------------------------------------------------------
// Kernel 3: softmax of row q over k in [q, 2048); single pass in registers;
// float4 loads; writes fp16 probs; zero-fills [q & ~127, q).
// ---------------------------------------------------------------------------
__global__ __launch_bounds__(256) void softmax_kernel() {
    const int q = blockIdx.x;
    const int b = blockIdx.y;
    const float* row = g_L + ((size_t)b * S_ + q) * S_;
    __half* ph = g_Ph + ((size_t)b * S_ + q) * S_;
    const int tid = threadIdx.x;

    __shared__ float red[8];
    __shared__ float bcast;

    const int a0 = (q + 3) & ~3;          // first 16B-aligned index >= q
    const int nscal = a0 - q;             // 0..3 scalar head elements

    float m = -3.0e38f;
    float sc = 0.f;
    if (tid < nscal) { sc = row[q + tid]; m = sc; }
    float4 v4[2];
    int nv = 0;
    for (int k = a0 + tid * 4; k < S_; k += 1024) {
        float4 v = *(const float4*)&row[k];
        v4[nv++] = v;
        m = fmaxf(m, fmaxf(fmaxf(v.x, v.y), fmaxf(v.z, v.w)));
    }
#pragma unroll
    for (int o = 16; o; o >>= 1) m = fmaxf(m, __shfl_xor_sync(0xffffffffu, m, o));
    if ((tid & 31) == 0) red[tid >> 5] = m;
    __syncthreads();
    if (tid == 0) {
        float v = red[0];
#pragma unroll
        for (int i = 1; i < 8; i++) v = fmaxf(v, red[i]);
        bcast = v;
    }
    __syncthreads();
    m = bcast;

    float s = 0.f;
    if (tid < nscal) { sc = expf(sc - m); s = sc; }
#pragma unroll
    for (int t = 0; t < 2; t++) {
        if (t < nv) {
            v4[t].x = expf(v4[t].x - m);
            v4[t].y = expf(v4[t].y - m);
            v4[t].z = expf(v4[t].z - m);
            v4[t].w = expf(v4[t].w - m);
            s += v4[t].x + v4[t].y + v4[t].z + v4[t].w;
        }
    }
#pragma unroll
    for (int o = 16; o; o >>= 1) s += __shfl_xor_sync(0xffffffffu, s, o);
    __syncthreads();
    if ((tid & 31) == 0) red[tid >> 5] = s;
    __syncthreads();
    if (tid == 0) {
        float v = 0.f;
#pragma unroll
        for (int i = 0; i < 8; i++) v += red[i];
        bcast = 1.0f / v;
    }
    __syncthreads();
    const float inv = bcast;

    if (tid < nscal) {
        ph[q + tid] = __float2half_rn(sc * inv);
    }
    {
        int nv2 = 0;
        for (int k = a0 + tid * 4; k < S_; k += 1024) {
            float4 v = v4[nv2++];
            union { __half bb[4]; uint2 u; } H;
            H.bb[0] = __float2half_rn(v.x * inv);
            H.bb[1] = __float2half_rn(v.y * inv);
            H.bb[2] = __float2half_rn(v.z * inv);
            H.bb[3] = __float2half_rn(v.w * inv);
            *(uint2*)&ph[k] = H.u;
        }
    }
    const __half z = __float2half_rn(0.f);
    for (int k = (q & ~127) + tid; k < q; k += 256) ph[k] = z;
}

// ---------------------------------------------------------------------------
extern "C" void kernel_launch(void* const* d_in, const int* in_sizes, int n_in,
                              void* d_out, int out_size) {
    const float* x = (const float*)d_in[0];   // [16, 2048, 64]
    const float* W = (const float*)d_in[1];   // [64, 3072]
    float* out = (float*)d_out;               // [16, 2048, 1024]
    (void)in_sizes; (void)n_in; (void)out_size;

    const int DYNB_QK = 3 * 4 * MATB + 1024;  // 197632
    const int DYNB_PV = 3 * 2 * MATB + 1024;  //  99328

    cudaFuncSetAttribute(attn_hmma_kernel<true>,
                         cudaFuncAttributeMaxDynamicSharedMemorySize, DYNB_QK);
    cudaFuncSetAttribute(attn_hmma_kernel<false>,
                         cudaFuncAttributeMaxDynamicSharedMemorySize, DYNB_PV);

    // 1) QKV projection (fp32 SIMT; q/k split-fp16, V^T fp16 fused)
    {
        dim3 grid(QKVW / 128, (B_ * S_) / 128);   // (24, 256)
        qkv_proj_kernel<<<grid, 256>>>(x, W);
    }
    // 2) logits = 0.25 * Q K^T (HMMA, packed upper-triangular tile grid)
    {
        dim3 grid(136, B_);                       // 136 live tiles per batch
        attn_hmma_kernel<true><<<grid, 256, DYNB_QK>>>(nullptr);
    }
    // 3) softmax -> fp16 probs
    {
        dim3 grid(S_, B_);                        // (2048, 16)
        softmax_kernel<<<grid, 256>>>();
    }
    // 4) out = P V (HMMA, single product)
    {
        dim3 grid(HEAD / 128, S_ / 128, B_);      // (8, 16, 16)
        attn_hmma_kernel<false><<<grid, 256, DYNB_PV>>>(out);
    }
}

// round 17
// speedup vs baseline: 1.5647x; 1.5647x over previous
#include <cuda_runtime.h>
#include <cuda_fp16.h>
#include <cstdint>
#include <cstddef>

// Problem constants
#define B_   16
#define S_   2048
#define DM   64
#define HEAD 1024
#define QKVW 3072   // 3 * HEAD

// ---------------------------------------------------------------------------
// Scratch (device globals; no runtime allocation allowed)
// ---------------------------------------------------------------------------
__device__ __align__(16) __half g_qh[(size_t)B_ * S_ * HEAD];
__device__ __align__(16) __half g_ql[(size_t)B_ * S_ * HEAD];
__device__ __align__(16) __half g_kh[(size_t)B_ * S_ * HEAD];
__device__ __align__(16) __half g_kl[(size_t)B_ * S_ * HEAD];
__device__ __align__(16) float  g_v [(size_t)B_ * S_ * HEAD];
__device__ __align__(16) __half g_vth[(size_t)B_ * HEAD * S_];  // V^T [b][n][k]
__device__ __align__(16) float  g_L [(size_t)B_ * S_ * S_];     // fp32 logits
__device__ __align__(16) __half g_Ph[(size_t)B_ * S_ * S_];     // probs (fp16)

// ---------------------------------------------------------------------------
// PTX helpers (sm_80-compatible: cp.async, ldmatrix, mma.sync)
// ---------------------------------------------------------------------------
__device__ __forceinline__ uint32_t smem_u32(const void* p) {
    return (uint32_t)__cvta_generic_to_shared(p);
}

__device__ __forceinline__ void cp_async16(uint32_t dst, const void* src) {
    asm volatile("cp.async.cg.shared.global [%0], [%1], 16;"
                 :: "r"(dst), "l"(src) : "memory");
}
__device__ __forceinline__ void cp_commit() {
    asm volatile("cp.async.commit_group;" ::: "memory");
}
__device__ __forceinline__ void cp_wait2() {
    asm volatile("cp.async.wait_group 2;" ::: "memory");
}
__device__ __forceinline__ void cp_wait1() {
    asm volatile("cp.async.wait_group 1;" ::: "memory");
}
__device__ __forceinline__ void cp_wait0() {
    asm volatile("cp.async.wait_group 0;" ::: "memory");
}

__device__ __forceinline__ void ldm_x4(uint32_t* f, uint32_t addr) {
    asm volatile("ldmatrix.sync.aligned.m8n8.x4.shared.b16 {%0,%1,%2,%3}, [%4];"
                 : "=r"(f[0]), "=r"(f[1]), "=r"(f[2]), "=r"(f[3]) : "r"(addr));
}

// fp32-accumulator HMMA (main product)
__device__ __forceinline__ void mma16816(float* c, const uint32_t* a,
                                         uint32_t b0, uint32_t b1) {
    asm volatile(
        "mma.sync.aligned.m16n8k16.row.col.f32.f16.f16.f32 "
        "{%0,%1,%2,%3}, {%4,%5,%6,%7}, {%8,%9}, {%0,%1,%2,%3};"
        : "+f"(c[0]), "+f"(c[1]), "+f"(c[2]), "+f"(c[3])
        : "r"(a[0]), "r"(a[1]), "r"(a[2]), "r"(a[3]), "r"(b0), "r"(b1));
}

// fp16-accumulator HMMA (correction products; small magnitudes)
__device__ __forceinline__ void mma16816_h(uint32_t* c, const uint32_t* a,
                                           uint32_t b0, uint32_t b1) {
    asm volatile(
        "mma.sync.aligned.m16n8k16.row.col.f16.f16.f16.f16 "
        "{%0,%1}, {%2,%3,%4,%5}, {%6,%7}, {%0,%1};"
        : "+r"(c[0]), "+r"(c[1])
        : "r"(a[0]), "r"(a[1]), "r"(a[2]), "r"(a[3]), "r"(b0), "r"(b1));
}

// ldmatrix lane address inside an SW128-swizzled tile (rows of 128 bytes).
// rowbase: first row of the 16-row block; ks: 16-element k-step (0..3).
__device__ __forceinline__ uint32_t ldm_addr(uint32_t matbase, int rowbase,
                                             int ks, int lane) {
    int j = lane >> 3, r = lane & 7;
    int row = rowbase + (j & 1) * 8 + r;
    uint32_t off = (uint32_t)(row * 128 + ks * 32 + (j >> 1) * 16);
    off ^= (off >> 3) & 0x70;
    return matbase + off;
}

// ---------------------------------------------------------------------------
// split-store helper: fp32 -> (hi, lo) fp16 pairs, 4 at a time (8B stores)
// ---------------------------------------------------------------------------
__device__ __forceinline__ void store_split4(__half* h, __half* l, const float* v) {
    union { __half b[4]; uint2 u; } H, L;
#pragma unroll
    for (int r = 0; r < 4; r++) {
        H.b[r] = __float2half_rn(v[r]);
        L.b[r] = __float2half_rn(v[r] - __half2float(H.b[r]));
    }
    *(uint2*)h = H.u;
    *(uint2*)l = L.u;
}

// ---------------------------------------------------------------------------
// Kernel 1: qkv = x @ W (fp32 SIMT), epilogue: q/k split-fp16, v fp32
// ---------------------------------------------------------------------------
__global__ __launch_bounds__(256, 2) void qkv_proj_kernel(const float* __restrict__ x,
                                                          const float* __restrict__ W) {
    __shared__ float xs[16][132];
    __shared__ float ws[16][132];
    const int m0 = blockIdx.y * 128;
    const int n0 = blockIdx.x * 128;
    const int tid = threadIdx.x;
    const int tx = tid & 15, ty = tid >> 4;

    float acc[8][8];
#pragma unroll
    for (int i = 0; i < 8; i++)
#pragma unroll
        for (int j = 0; j < 8; j++) acc[i][j] = 0.f;

    for (int d0 = 0; d0 < DM; d0 += 16) {
#pragma unroll
        for (int t = 0; t < 2; t++) {
            int idx = tid + t * 256;
            int row = idx >> 2, dg = (idx & 3) * 4;
            float4 v = *(const float4*)&x[(size_t)(m0 + row) * DM + d0 + dg];
            xs[dg + 0][row] = v.x; xs[dg + 1][row] = v.y;
            xs[dg + 2][row] = v.z; xs[dg + 3][row] = v.w;
        }
#pragma unroll
        for (int t = 0; t < 2; t++) {
            int idx = tid + t * 256;
            int kk = idx >> 5, ng = (idx & 31) * 4;
            *(float4*)&ws[kk][ng] = *(const float4*)&W[(size_t)(d0 + kk) * QKVW + n0 + ng];
        }
        __syncthreads();
#pragma unroll
        for (int d = 0; d < 16; d++) {
            float a[8], bb[8];
            *(float4*)&a[0]  = *(const float4*)&xs[d][ty * 4];
            *(float4*)&a[4]  = *(const float4*)&xs[d][64 + ty * 4];
            *(float4*)&bb[0] = *(const float4*)&ws[d][tx * 4];
            *(float4*)&bb[4] = *(const float4*)&ws[d][64 + tx * 4];
#pragma unroll
            for (int i = 0; i < 8; i++)
#pragma unroll
                for (int j = 0; j < 8; j++) acc[i][j] += a[i] * bb[j];
        }
        __syncthreads();
    }

    const int region = n0 >> 10;   // 0=q, 1=k, 2=v (128-tiles never straddle)
    const int nn = n0 & 1023;
#pragma unroll
    for (int i = 0; i < 8; i++) {
        int r = m0 + ((i < 4) ? (ty * 4 + i) : (64 + ty * 4 + i - 4));
        if (region == 2) {
            float* o = g_v + (size_t)r * HEAD + nn;
            *(float4*)&o[tx * 4]      = *(float4*)&acc[i][0];
            *(float4*)&o[64 + tx * 4] = *(float4*)&acc[i][4];
        } else {
            __half* hb = (region == 0 ? g_qh : g_kh) + (size_t)r * HEAD + nn;
            __half* lb = (region == 0 ? g_ql : g_kl) + (size_t)r * HEAD + nn;
            store_split4(hb + tx * 4,      lb + tx * 4,      &acc[i][0]);
            store_split4(hb + 64 + tx * 4, lb + 64 + tx * 4, &acc[i][4]);
        }
    }
}

// ---------------------------------------------------------------------------
// Kernel 2: transpose V: g_v [b*S + m][n] -> g_vth [b][n][m] (fp16)
// ---------------------------------------------------------------------------
__global__ __launch_bounds__(256) void vtrans_kernel() {
    __shared__ float s[64][65];
    const int m0 = blockIdx.x * 64, n0 = blockIdx.y * 64, b = blockIdx.z;
    const float* src = g_v + ((size_t)(b * S_ + m0)) * HEAD + n0;
    const int tid = threadIdx.x;

#pragma unroll
    for (int t = 0; t < 4; t++) {
        int idx = t * 256 + tid;
        int row = idx >> 4, c4 = (idx & 15) * 4;
        float4 v = *(const float4*)&src[(size_t)row * HEAD + c4];
        s[row][c4] = v.x; s[row][c4 + 1] = v.y; s[row][c4 + 2] = v.z; s[row][c4 + 3] = v.w;
    }
    __syncthreads();

#pragma unroll
    for (int t = 0; t < 4; t++) {
        int idx = t * 256 + tid;
        int n = idx >> 4, m4 = (idx & 15) * 4;
        union { __half b[4]; uint2 u; } H;
#pragma unroll
        for (int r = 0; r < 4; r++) H.b[r] = __float2half_rn(s[m4 + r][n]);
        size_t o = ((size_t)(b * HEAD + n0 + n)) * S_ + m0 + m4;
        *(uint2*)&g_vth[o] = H.u;
    }
}

// ---------------------------------------------------------------------------
// HMMA split-fp16 GEMM, 128x128 CTA tile, 256 threads (8 warps of 64x32),
// K-chunks of 64, 3-stage cp.async pipeline, SW128 smem.
//   IS_QK: 4 matrices (qh,ql,kh,kl): f32 hh + f16-acc (al*bh + ah*bl)
//          -> g_L x0.25  [packed upper-triangular tile grid; 1 CTA/SM]
//   else : 2 matrices (Ph,Vh): single f32 hh product -> pv_out
//          [k starts at 128-aligned diagonal; 2 CTAs/SM for latency overlap]
// ---------------------------------------------------------------------------
#define MATB   16384                  // 128 rows x 128B

template <bool IS_QK>
__global__ void __launch_bounds__(256, IS_QK ? 1 : 2)
attn_hmma_kernel(float* __restrict__ pv_out) {
    constexpr int NMAT  = IS_QK ? 4 : 2;
    constexpr int STAGE = NMAT * MATB;

    int bm, bn, b;
    if (IS_QK) {
        // packed upper-tri grid: per batch, tiles (bm, bn) with bn >= bm
        int t = blockIdx.x;
        b = blockIdx.y;
        bm = 0;
#pragma unroll 1
        for (; bm < 16; bm++) {
            int cnt = 16 - bm;
            if (t < cnt) break;
            t -= cnt;
        }
        bn = bm + t;
    } else {
        bn = blockIdx.x; bm = blockIdx.y; b = blockIdx.z;
    }

    extern __shared__ __align__(16) char dyn[];
    const uint32_t dynb = smem_u32(dyn);
    const uint32_t tileb = (dynb + 1023) & ~1023u;

    const int tid = threadIdx.x, wid = tid >> 5, lane = tid & 31;
    const int m0 = bm * 128, n0 = bn * 128;
    const int m_off = (wid >> 2) * 64;   // warp rows: 0 or 64
    const int n_off = (wid & 3) * 32;    // warp cols: 0,32,64,96

    const __half* gmat[NMAT];
    size_t strd;
    int kstart, NC;
    if (IS_QK) {
        size_t ab  = ((size_t)(b * S_ + m0)) * HEAD;
        size_t bb2 = ((size_t)(b * S_ + n0)) * HEAD;
        gmat[0] = g_qh + ab; gmat[1] = g_ql + ab;
        gmat[2] = g_kh + bb2; gmat[3] = g_kl + bb2;
        strd = HEAD; kstart = 0; NC = HEAD / 64;
    } else {
        size_t ab  = ((size_t)(b * S_ + m0)) * S_;
        size_t bb2 = ((size_t)(b * HEAD + n0)) * S_;
        gmat[0] = g_Ph + ab; gmat[1] = g_vth + bb2;
        strd = S_; kstart = m0; NC = (S_ - m0) / 64;
    }

    float acc[4][4][4];          // f32 main accumulators
    uint32_t accl[4][4][2];      // f16x2 correction accumulators (QK only)
#pragma unroll
    for (int i = 0; i < 4; i++)
#pragma unroll
        for (int p = 0; p < 4; p++) {
#pragma unroll
            for (int r = 0; r < 4; r++) acc[i][p][r] = 0.f;
            if (IS_QK) { accl[i][p][0] = 0u; accl[i][p][1] = 0u; }
        }

    // chunk loader: NMAT matrices x 128 rows x 64 fp16, SW128, cp.async
    auto load_chunk = [&](int c, int buf) {
        const int k0 = kstart + c * 64;
        uint32_t sb = tileb + buf * STAGE;
#pragma unroll
        for (int mat = 0; mat < NMAT; mat++) {
            const __half* g = gmat[mat] + k0;
            uint32_t mb = sb + mat * MATB;
#pragma unroll
            for (int t = 0; t < 4; t++) {
                int idx = t * 256 + tid;
                int row = idx >> 3, pc = idx & 7;
                uint32_t off = (uint32_t)(row * 128 + pc * 16);
                off ^= (off >> 3) & 0x70;
                cp_async16(mb + off, g + (size_t)row * strd + pc * 8);
            }
        }
        cp_commit();
    };

    load_chunk(0, 0);
    if (NC > 1) load_chunk(1, 1);

    for (int c = 0; c < NC; ++c) {
        const int buf = c % 3;
        if (c + 2 < NC) load_chunk(c + 2, (c + 2) % 3);
        {
            int pend = NC - 1 - c; if (pend > 2) pend = 2;
            if (pend == 2) cp_wait2();
            else if (pend == 1) cp_wait1();
            else cp_wait0();
        }
        __syncthreads();

        const uint32_t base = tileb + buf * STAGE;
        const uint32_t bAh = base;
        const uint32_t bAl = base + MATB;                       // QK only
        const uint32_t bBh = base + (IS_QK ? 2 : 1) * MATB;
        const uint32_t bBl = base + 3 * MATB;                   // QK only

#pragma unroll
        for (int ks = 0; ks < 4; ks++) {
            uint32_t ah[4][4], al[4][4];
#pragma unroll
            for (int i = 0; i < 4; i++) {
                ldm_x4(ah[i], ldm_addr(bAh, m_off + i * 16, ks, lane));
                if (IS_QK) ldm_x4(al[i], ldm_addr(bAl, m_off + i * 16, ks, lane));
            }
#pragma unroll
            for (int p2 = 0; p2 < 2; p2++) {
                uint32_t bh[4], bl[4];
                ldm_x4(bh, ldm_addr(bBh, n_off + p2 * 16, ks, lane));
                if (IS_QK) ldm_x4(bl, ldm_addr(bBl, n_off + p2 * 16, ks, lane));
#pragma unroll
                for (int i = 0; i < 4; i++)
#pragma unroll
                    for (int sb2 = 0; sb2 < 2; sb2++) {
                        const int p = p2 * 2 + sb2;
                        mma16816(acc[i][p], ah[i], bh[sb2], bh[2 + sb2]);
                        if (IS_QK) {
                            mma16816_h(accl[i][p], al[i], bh[sb2], bh[2 + sb2]);
                            mma16816_h(accl[i][p], ah[i], bl[sb2], bl[2 + sb2]);
                        }
                    }
            }
        }
        __syncthreads();
    }

    // epilogue
#pragma unroll
    for (int i = 0; i < 4; i++) {
        int gm = m0 + m_off + i * 16 + (lane >> 2);
#pragma unroll
        for (int p = 0; p < 4; p++) {
            int gn = n0 + n_off + p * 8 + (lane & 3) * 2;
            if (IS_QK) {
                float2 c0 = __half22float2(*(__half2*)&accl[i][p][0]);
                float2 c1 = __half22float2(*(__half2*)&accl[i][p][1]);
                float2 lo = make_float2(0.25f * (acc[i][p][0] + c0.x),
                                        0.25f * (acc[i][p][1] + c0.y));
                float2 hi = make_float2(0.25f * (acc[i][p][2] + c1.x),
                                        0.25f * (acc[i][p][3] + c1.y));
                float* d0 = g_L + ((size_t)(b * S_ + gm)) * S_ + gn;
                *(float2*)d0 = lo;
                *(float2*)(d0 + 8 * S_) = hi;
            } else {
                float2 lo = make_float2(acc[i][p][0], acc[i][p][1]);
                float2 hi = make_float2(acc[i][p][2], acc[i][p][3]);
                float* d0 = pv_out + ((size_t)(b * S_ + gm)) * HEAD + gn;
                *(float2*)d0 = lo;
                *(float2*)(d0 + 8 * HEAD) = hi;
            }
        }
    }
}

// ---------------------------------------------------------------------------
// Kernel 4: softmax of row q over k in [q, 2048); single pass in registers;
// float4 loads; writes fp16 probs; zero-fills [q & ~127, q).
// ---------------------------------------------------------------------------
__global__ __launch_bounds__(256) void softmax_kernel() {
    const int q = blockIdx.x;
    const int b = blockIdx.y;
    const float* row = g_L + ((size_t)b * S_ + q) * S_;
    __half* ph = g_Ph + ((size_t)b * S_ + q) * S_;
    const int tid = threadIdx.x;

    __shared__ float red[8];
    __shared__ float bcast;

    const int a0 = (q + 3) & ~3;          // first 16B-aligned index >= q
    const int nscal = a0 - q;             // 0..3 scalar head elements

    float m = -3.0e38f;
    float sc = 0.f;
    if (tid < nscal) { sc = row[q + tid]; m = sc; }
    float4 v4[2];
    int nv = 0;
    for (int k = a0 + tid * 4; k < S_; k += 1024) {
        float4 v = *(const float4*)&row[k];
        v4[nv++] = v;
        m = fmaxf(m, fmaxf(fmaxf(v.x, v.y), fmaxf(v.z, v.w)));
    }
#pragma unroll
    for (int o = 16; o; o >>= 1) m = fmaxf(m, __shfl_xor_sync(0xffffffffu, m, o));
    if ((tid & 31) == 0) red[tid >> 5] = m;
    __syncthreads();
    if (tid == 0) {
        float v = red[0];
#pragma unroll
        for (int i = 1; i < 8; i++) v = fmaxf(v, red[i]);
        bcast = v;
    }
    __syncthreads();
    m = bcast;

    float s = 0.f;
    if (tid < nscal) { sc = expf(sc - m); s = sc; }
#pragma unroll
    for (int t = 0; t < 2; t++) {
        if (t < nv) {
            v4[t].x = expf(v4[t].x - m);
            v4[t].y = expf(v4[t].y - m);
            v4[t].z = expf(v4[t].z - m);
            v4[t].w = expf(v4[t].w - m);
            s += v4[t].x + v4[t].y + v4[t].z + v4[t].w;
        }
    }
#pragma unroll
    for (int o = 16; o; o >>= 1) s += __shfl_xor_sync(0xffffffffu, s, o);
    __syncthreads();
    if ((tid & 31) == 0) red[tid >> 5] = s;
    __syncthreads();
    if (tid == 0) {
        float v = 0.f;
#pragma unroll
        for (int i = 0; i < 8; i++) v += red[i];
        bcast = 1.0f / v;
    }
    __syncthreads();
    const float inv = bcast;

    if (tid < nscal) {
        ph[q + tid] = __float2half_rn(sc * inv);
    }
    {
        int nv2 = 0;
        for (int k = a0 + tid * 4; k < S_; k += 1024) {
            float4 v = v4[nv2++];
            union { __half bb[4]; uint2 u; } H;
            H.bb[0] = __float2half_rn(v.x * inv);
            H.bb[1] = __float2half_rn(v.y * inv);
            H.bb[2] = __float2half_rn(v.z * inv);
            H.bb[3] = __float2half_rn(v.w * inv);
            *(uint2*)&ph[k] = H.u;
        }
    }
    const __half z = __float2half_rn(0.f);
    for (int k = (q & ~127) + tid; k < q; k += 256) ph[k] = z;
}

// ---------------------------------------------------------------------------
extern "C" void kernel_launch(void* const* d_in, const int* in_sizes, int n_in,
                              void* d_out, int out_size) {
    const float* x = (const float*)d_in[0];   // [16, 2048, 64]
    const float* W = (const float*)d_in[1];   // [64, 3072]
    float* out = (float*)d_out;               // [16, 2048, 1024]
    (void)in_sizes; (void)n_in; (void)out_size;

    const int DYNB_QK = 3 * 4 * MATB + 1024;  // 197632
    const int DYNB_PV = 3 * 2 * MATB + 1024;  //  99328 (x2 CTAs = 198656, fits)

    cudaFuncSetAttribute(attn_hmma_kernel<true>,
                         cudaFuncAttributeMaxDynamicSharedMemorySize, DYNB_QK);
    cudaFuncSetAttribute(attn_hmma_kernel<false>,
                         cudaFuncAttributeMaxDynamicSharedMemorySize, DYNB_PV);

    // 1) QKV projection (fp32 SIMT; split-fp16 q/k, fp32 v)
    {
        dim3 grid(QKVW / 128, (B_ * S_) / 128);   // (24, 256)
        qkv_proj_kernel<<<grid, 256>>>(x, W);
    }
    // 2) V transpose (fp16)
    {
        dim3 grid(S_ / 64, HEAD / 64, B_);        // (32, 16, 16)
        vtrans_kernel<<<grid, 256>>>();
    }
    // 3) logits = 0.25 * Q K^T (HMMA, packed upper-triangular tile grid)
    {
        dim3 grid(136, B_);                       // 136 live tiles per batch
        attn_hmma_kernel<true><<<grid, 256, DYNB_QK>>>(nullptr);
    }
    // 4) softmax -> fp16 probs
    {
        dim3 grid(S_, B_);                        // (2048, 16)
        softmax_kernel<<<grid, 256>>>();
    }
    // 5) out = P V (HMMA, single product, 2 CTAs/SM)
    {
        dim3 grid(HEAD / 128, S_ / 128, B_);      // (8, 16, 16)
        attn_hmma_kernel<false><<<grid, 256, DYNB_PV>>>(out);
    }
}